// round 2
// baseline (speedup 1.0000x reference)
#include <cuda_runtime.h>

#define NB 2
#define LQS 2048
#define LKS 2048
#define DM 1024
#define NH 16
#define HD 64

// Scratch: Q/K/V in (n, h, l, dd) layout
__device__ float g_q[NB * NH * LQS * HD];
__device__ float g_k[NB * NH * LKS * HD];
__device__ float g_v[NB * NH * LKS * HD];
__device__ float g_scale[8];
__device__ int   g_len[8];

// ---------------------------------------------------------------------------
// Count valid keys per batch -> scale = 1/sqrt(valid), len = valid count
// padding_mask is int32 (bool converted by harness): nonzero = padded.
// ---------------------------------------------------------------------------
__global__ void count_kernel(const int* __restrict__ pad) {
    int n = blockIdx.x;
    __shared__ int cnt;
    if (threadIdx.x == 0) cnt = 0;
    __syncthreads();
    int c = 0;
    for (int i = threadIdx.x; i < LKS; i += blockDim.x)
        if (pad[n * LKS + i] == 0) c++;
    atomicAdd(&cnt, c);
    __syncthreads();
    if (threadIdx.x == 0) {
        g_len[n] = cnt;
        g_scale[n] = rsqrtf((float)cnt);
    }
}

// ---------------------------------------------------------------------------
// Projection GEMM: Y = X @ W^T, X (M=NB*L, K=1024) row-major, W (1024,1024)
// row-major (torch Linear). Output scattered to (n, h, l, dd) layout.
// Tile 128x128x8, 256 threads, 8x8 per-thread microtile.
// ---------------------------------------------------------------------------
__global__ void __launch_bounds__(256) proj_kernel(
    const float* __restrict__ X, const float* __restrict__ W,
    float* __restrict__ Y) {
    __shared__ float As[8][128];
    __shared__ float Bs[8][128];

    const int bm = blockIdx.y * 128;
    const int bn = blockIdx.x * 128;
    const int tid = threadIdx.x;
    const int a = (tid >> 4) * 8;   // row offset in tile
    const int b = (tid & 15) * 8;   // col offset in tile
    const int lr = tid >> 1;        // load row 0..127
    const int lc = (tid & 1) * 4;   // load col 0 or 4

    float acc[8][8];
#pragma unroll
    for (int i = 0; i < 8; i++)
#pragma unroll
        for (int j = 0; j < 8; j++) acc[i][j] = 0.f;

    const float* Xp = X + (size_t)(bm + lr) * DM + lc;
    const float* Wp = W + (size_t)(bn + lr) * DM + lc;

    for (int k0 = 0; k0 < DM; k0 += 8) {
        float4 av = *(const float4*)(Xp + k0);
        float4 bv = *(const float4*)(Wp + k0);
        As[lc + 0][lr] = av.x; As[lc + 1][lr] = av.y;
        As[lc + 2][lr] = av.z; As[lc + 3][lr] = av.w;
        Bs[lc + 0][lr] = bv.x; Bs[lc + 1][lr] = bv.y;
        Bs[lc + 2][lr] = bv.z; Bs[lc + 3][lr] = bv.w;
        __syncthreads();
#pragma unroll
        for (int k = 0; k < 8; k++) {
            float ar[8], br[8];
            *(float4*)&ar[0] = *(const float4*)&As[k][a];
            *(float4*)&ar[4] = *(const float4*)&As[k][a + 4];
            *(float4*)&br[0] = *(const float4*)&Bs[k][b];
            *(float4*)&br[4] = *(const float4*)&Bs[k][b + 4];
#pragma unroll
            for (int i = 0; i < 8; i++)
#pragma unroll
                for (int j = 0; j < 8; j++)
                    acc[i][j] += ar[i] * br[j];
        }
        __syncthreads();
    }

#pragma unroll
    for (int i = 0; i < 8; i++) {
        int m = bm + a + i;
        int n = m >> 11;          // / 2048
        int l = m & (LQS - 1);
#pragma unroll
        for (int j = 0; j < 8; j++) {
            int col = bn + b + j;
            int h = col >> 6;
            int dd = col & 63;
            Y[((size_t)((n * NH + h) * LQS) + l) * HD + dd] = acc[i][j];
        }
    }
}

// ---------------------------------------------------------------------------
// Flash attention: one block = (query tile of 64, head h, batch n).
// Online softmax, stats in registers (replicated across 16-lane row groups).
// Smem (dynamic): Qs[64][68] (d-major), Ks[64][68] (d-major, reused for P^T),
// Vs[64][68] (key-major). 256 threads, each owns a 4x4 microtile.
// ---------------------------------------------------------------------------
__global__ void __launch_bounds__(256) attn_kernel(
    const int* __restrict__ pad, float* __restrict__ out) {
    extern __shared__ float smdyn[];
    float (*Qs)[68] = (float(*)[68])smdyn;                 // [dd][q]
    float (*Ks)[68] = (float(*)[68])(smdyn + 64 * 68);     // [dd][k] -> [k][q] (P)
    float (*Vs)[68] = (float(*)[68])(smdyn + 2 * 64 * 68); // [k][dd]
    __shared__ int pm[64];

    const int qt = blockIdx.x;
    const int h = blockIdx.y;
    const int n = blockIdx.z;
    const int tid = threadIdx.x;
    const int r0 = (tid >> 4) * 4;   // query rows r0..r0+3
    const int c0 = (tid & 15) * 4;   // key cols / d cols c0..c0+3

    const float* qbase = g_q + ((size_t)(n * NH + h) * LQS + qt * 64) * HD;
    for (int idx = tid; idx < 64 * 64; idx += 256) {
        int r = idx >> 6, dd = idx & 63;
        Qs[dd][r] = qbase[r * HD + dd];
    }

    const float sc = g_scale[n];
    const int len = g_len[n];
    const int ktmax = min(qt, (len - 1) >> 6);  // inclusive; tail padding

    float mrow[4], lrow[4], O[4][4];
#pragma unroll
    for (int i = 0; i < 4; i++) {
        mrow[i] = -1e30f; lrow[i] = 0.f;
#pragma unroll
        for (int j = 0; j < 4; j++) O[i][j] = 0.f;
    }

    for (int kt = 0; kt <= ktmax; kt++) {
        const float* kbase = g_k + ((size_t)(n * NH + h) * LKS + kt * 64) * HD;
        const float* vbase = g_v + ((size_t)(n * NH + h) * LKS + kt * 64) * HD;
        __syncthreads();  // previous iteration done with Ks(P)/Vs
        for (int idx = tid; idx < 64 * 64; idx += 256) {
            int r = idx >> 6, dd = idx & 63;
            Ks[dd][r] = kbase[r * HD + dd];
            Vs[r][dd] = vbase[r * HD + dd];
        }
        if (tid < 64) pm[tid] = pad[n * LKS + kt * 64 + tid];
        __syncthreads();

        // S = Q K^T (4x4 microtile)
        float S[4][4];
#pragma unroll
        for (int i = 0; i < 4; i++)
#pragma unroll
            for (int j = 0; j < 4; j++) S[i][j] = 0.f;
#pragma unroll 4
        for (int kk = 0; kk < 64; kk++) {
            float4 qv = *(const float4*)&Qs[kk][r0];
            float4 kv = *(const float4*)&Ks[kk][c0];
            float qa[4] = {qv.x, qv.y, qv.z, qv.w};
            float ka[4] = {kv.x, kv.y, kv.z, kv.w};
#pragma unroll
            for (int i = 0; i < 4; i++)
#pragma unroll
                for (int j = 0; j < 4; j++)
                    S[i][j] += qa[i] * ka[j];
        }

        // scale + mask + local row max
        const int qg0 = qt * 64 + r0;
        const int kg0 = kt * 64 + c0;
        float tmax[4];
#pragma unroll
        for (int i = 0; i < 4; i++) {
            tmax[i] = -1e30f;
#pragma unroll
            for (int j = 0; j < 4; j++) {
                bool masked = (kg0 + j > qg0 + i) || (pm[c0 + j] != 0);
                float v = masked ? -1e30f : S[i][j] * sc;
                S[i][j] = v;
                tmax[i] = fmaxf(tmax[i], v);
            }
        }
        // reduce max across the 16 lanes of this row group
#pragma unroll
        for (int off = 8; off >= 1; off >>= 1)
#pragma unroll
            for (int i = 0; i < 4; i++)
                tmax[i] = fmaxf(tmax[i],
                    __shfl_xor_sync(0xffffffffu, tmax[i], off, 16));

        float alpha[4], rsum[4];
#pragma unroll
        for (int i = 0; i < 4; i++) {
            float nm = fmaxf(mrow[i], tmax[i]);
            alpha[i] = __expf(mrow[i] - nm);
            mrow[i] = nm;
            float s_ = 0.f;
#pragma unroll
            for (int j = 0; j < 4; j++) {
                float p = __expf(S[i][j] - nm);
                S[i][j] = p;
                s_ += p;
            }
            rsum[i] = s_;
        }
#pragma unroll
        for (int off = 8; off >= 1; off >>= 1)
#pragma unroll
            for (int i = 0; i < 4; i++)
                rsum[i] += __shfl_xor_sync(0xffffffffu, rsum[i], off, 16);
#pragma unroll
        for (int i = 0; i < 4; i++) {
            lrow[i] = lrow[i] * alpha[i] + rsum[i];
#pragma unroll
            for (int j = 0; j < 4; j++) O[i][j] *= alpha[i];
        }

        __syncthreads();  // everyone done reading Ks
        // store P transposed into K buffer: Pt[key][q]
#pragma unroll
        for (int j = 0; j < 4; j++)
#pragma unroll
            for (int i = 0; i < 4; i++)
                Ks[c0 + j][r0 + i] = S[i][j];
        __syncthreads();

        // O += P V (inner over keys kk)
#pragma unroll 4
        for (int kk = 0; kk < 64; kk++) {
            float4 pv = *(const float4*)&Ks[kk][r0];
            float4 vv = *(const float4*)&Vs[kk][c0];
            float pa[4] = {pv.x, pv.y, pv.z, pv.w};
            float va[4] = {vv.x, vv.y, vv.z, vv.w};
#pragma unroll
            for (int i = 0; i < 4; i++)
#pragma unroll
                for (int j = 0; j < 4; j++)
                    O[i][j] += pa[i] * va[j];
        }
    }

    // epilogue: normalize and write (n, l, h*64+dd)
#pragma unroll
    for (int i = 0; i < 4; i++) {
        float inv = 1.f / lrow[i];
        int qg = qt * 64 + r0 + i;
        float* op = out + ((size_t)n * LQS + qg) * DM + h * HD + c0;
        op[0] = O[i][0] * inv;
        op[1] = O[i][1] * inv;
        op[2] = O[i][2] * inv;
        op[3] = O[i][3] * inv;
    }
}

// ---------------------------------------------------------------------------
extern "C" void kernel_launch(void* const* d_in, const int* in_sizes, int n_in,
                              void* d_out, int out_size) {
    const float* query = (const float*)d_in[0];
    const float* key   = (const float*)d_in[1];
    const float* Wq    = (const float*)d_in[2];
    const float* Wk    = (const float*)d_in[3];
    const float* Wv    = (const float*)d_in[4];
    const int* pad     = (const int*)d_in[6];   // bool -> int32
    float* out = (float*)d_out;

    const int attn_smem = 3 * 64 * 68 * 4;  // 52224 B
    cudaFuncSetAttribute(attn_kernel,
                         cudaFuncAttributeMaxDynamicSharedMemorySize, attn_smem);

    void *pq, *pk, *pv;
    cudaGetSymbolAddress(&pq, g_q);
    cudaGetSymbolAddress(&pk, g_k);
    cudaGetSymbolAddress(&pv, g_v);

    count_kernel<<<NB, 256>>>(pad);

    dim3 pg(DM / 128, (NB * LQS) / 128);  // (8, 32)
    proj_kernel<<<pg, 256>>>(query, Wq, (float*)pq);
    proj_kernel<<<pg, 256>>>(key,   Wk, (float*)pk);
    proj_kernel<<<pg, 256>>>(key,   Wv, (float*)pv);

    dim3 ag(LQS / 64, NH, NB);  // (32, 16, 2)
    attn_kernel<<<ag, 256, attn_smem>>>(pad, out);
}

// round 3
// speedup vs baseline: 1.0377x; 1.0377x over previous
#include <cuda_runtime.h>

#define NB 2
#define LQS 2048
#define LKS 2048
#define DM 1024
#define NH 16
#define HD 64

typedef unsigned long long u64;

// Scratch: Q/K/V in (n, h, l, dd) layout
__device__ float g_q[NB * NH * LQS * HD];
__device__ float g_k[NB * NH * LKS * HD];
__device__ float g_v[NB * NH * LKS * HD];
__device__ float g_scale[8];
__device__ int   g_len[8];

// ---- packed f32x2 helpers ------------------------------------------------
__device__ __forceinline__ u64 pack2(float x, float y) {
    u64 r; asm("mov.b64 %0, {%1,%2};" : "=l"(r) : "f"(x), "f"(y)); return r;
}
__device__ __forceinline__ u64 bcast2(float x) {
    u64 r; asm("mov.b64 %0, {%1,%1};" : "=l"(r) : "f"(x)); return r;
}
__device__ __forceinline__ void unpack2(u64 v, float& x, float& y) {
    asm("mov.b64 {%0,%1}, %2;" : "=f"(x), "=f"(y) : "l"(v));
}
__device__ __forceinline__ void ffma2(u64& d, u64 a, u64 b) {
    asm("fma.rn.f32x2 %0, %1, %2, %0;" : "+l"(d) : "l"(a), "l"(b));
}
__device__ __forceinline__ void fmul2(u64& d, u64 a) {
    asm("mul.rn.f32x2 %0, %0, %1;" : "+l"(d) : "l"(a));
}

// ---------------------------------------------------------------------------
// Count valid keys per batch -> scale = 1/sqrt(valid), len = valid count
// padding_mask is int32 (bool converted by harness): nonzero = padded.
// ---------------------------------------------------------------------------
__global__ void count_kernel(const int* __restrict__ pad) {
    int n = blockIdx.x;
    __shared__ int cnt;
    if (threadIdx.x == 0) cnt = 0;
    __syncthreads();
    int c = 0;
    for (int i = threadIdx.x; i < LKS; i += blockDim.x)
        if (pad[n * LKS + i] == 0) c++;
    atomicAdd(&cnt, c);
    __syncthreads();
    if (threadIdx.x == 0) {
        g_len[n] = cnt;
        g_scale[n] = rsqrtf((float)cnt);
    }
}

// ---------------------------------------------------------------------------
// Projection GEMM: Y = X @ W^T, 128x128x8 tile, 256 thr, 8x8 microtile,
// inner product via packed fma.rn.f32x2 (acc packed along j).
// ---------------------------------------------------------------------------
__global__ void __launch_bounds__(256) proj_kernel(
    const float* __restrict__ X, const float* __restrict__ W,
    float* __restrict__ Y) {
    __shared__ float As[8][128];
    __shared__ float Bs[8][128];

    const int bm = blockIdx.y * 128;
    const int bn = blockIdx.x * 128;
    const int tid = threadIdx.x;
    const int a = (tid >> 4) * 8;
    const int b = (tid & 15) * 8;
    const int lr = tid >> 1;
    const int lc = (tid & 1) * 4;

    u64 acc[8][4];
#pragma unroll
    for (int i = 0; i < 8; i++)
#pragma unroll
        for (int j = 0; j < 4; j++) acc[i][j] = 0ull;

    const float* Xp = X + (size_t)(bm + lr) * DM + lc;
    const float* Wp = W + (size_t)(bn + lr) * DM + lc;

    for (int k0 = 0; k0 < DM; k0 += 8) {
        float4 av = *(const float4*)(Xp + k0);
        float4 bv = *(const float4*)(Wp + k0);
        As[lc + 0][lr] = av.x; As[lc + 1][lr] = av.y;
        As[lc + 2][lr] = av.z; As[lc + 3][lr] = av.w;
        Bs[lc + 0][lr] = bv.x; Bs[lc + 1][lr] = bv.y;
        Bs[lc + 2][lr] = bv.z; Bs[lc + 3][lr] = bv.w;
        __syncthreads();
#pragma unroll
        for (int k = 0; k < 8; k++) {
            float ar[8];
            *(float4*)&ar[0] = *(const float4*)&As[k][a];
            *(float4*)&ar[4] = *(const float4*)&As[k][a + 4];
            // B pairs straight from smem (16B-aligned)
            ulonglong2 b01 = *(const ulonglong2*)&Bs[k][b];
            ulonglong2 b23 = *(const ulonglong2*)&Bs[k][b + 4];
            u64 bp[4] = {b01.x, b01.y, b23.x, b23.y};
#pragma unroll
            for (int i = 0; i < 8; i++) {
                u64 ai = bcast2(ar[i]);
#pragma unroll
                for (int j = 0; j < 4; j++)
                    ffma2(acc[i][j], ai, bp[j]);
            }
        }
        __syncthreads();
    }

#pragma unroll
    for (int i = 0; i < 8; i++) {
        int m = bm + a + i;
        int n = m >> 11;
        int l = m & (LQS - 1);
#pragma unroll
        for (int j = 0; j < 4; j++) {
            int col = bn + b + 2 * j;
            int h = col >> 6;
            int dd = col & 63;
            float x, y;
            unpack2(acc[i][j], x, y);
            float* yp = &Y[((size_t)((n * NH + h) * LQS) + l) * HD + dd];
            yp[0] = x; yp[1] = y;   // dd, dd+1 stay within one head (HD=64 even)
        }
    }
}

// ---------------------------------------------------------------------------
// Flash attention: one block = (query tile 64, head, batch). 256 thr, 4x4
// microtile; matmuls via fma.rn.f32x2 (acc packed along j).
// ---------------------------------------------------------------------------
__global__ void __launch_bounds__(256) attn_kernel(
    const int* __restrict__ pad, float* __restrict__ out) {
    extern __shared__ float smdyn[];
    float (*Qs)[68] = (float(*)[68])smdyn;                 // [dd][q]
    float (*Ks)[68] = (float(*)[68])(smdyn + 64 * 68);     // [dd][k] -> P^T[k][q]
    float (*Vs)[68] = (float(*)[68])(smdyn + 2 * 64 * 68); // [k][dd]
    __shared__ int pm[64];

    const int qt = blockIdx.x;
    const int h = blockIdx.y;
    const int n = blockIdx.z;
    const int tid = threadIdx.x;
    const int r0 = (tid >> 4) * 4;
    const int c0 = (tid & 15) * 4;

    const float* qbase = g_q + ((size_t)(n * NH + h) * LQS + qt * 64) * HD;
    for (int idx = tid; idx < 64 * 64; idx += 256) {
        int r = idx >> 6, dd = idx & 63;
        Qs[dd][r] = qbase[r * HD + dd];
    }

    const float sc = g_scale[n];
    const int len = g_len[n];
    const int ktmax = min(qt, (len - 1) >> 6);

    float mrow[4], lrow[4];
    u64 O[4][2];
#pragma unroll
    for (int i = 0; i < 4; i++) {
        mrow[i] = -1e30f; lrow[i] = 0.f;
        O[i][0] = 0ull; O[i][1] = 0ull;
    }

    for (int kt = 0; kt <= ktmax; kt++) {
        const float* kbase = g_k + ((size_t)(n * NH + h) * LKS + kt * 64) * HD;
        const float* vbase = g_v + ((size_t)(n * NH + h) * LKS + kt * 64) * HD;
        __syncthreads();
        for (int idx = tid; idx < 64 * 64; idx += 256) {
            int r = idx >> 6, dd = idx & 63;
            Ks[dd][r] = kbase[r * HD + dd];
            Vs[r][dd] = vbase[r * HD + dd];
        }
        if (tid < 64) pm[tid] = pad[n * LKS + kt * 64 + tid];
        __syncthreads();

        // S = Q K^T, packed along key-cols
        u64 Sp[4][2];
#pragma unroll
        for (int i = 0; i < 4; i++) { Sp[i][0] = 0ull; Sp[i][1] = 0ull; }
#pragma unroll 4
        for (int kk = 0; kk < 64; kk++) {
            float4 qv = *(const float4*)&Qs[kk][r0];
            ulonglong2 kv = *(const ulonglong2*)&Ks[kk][c0];
            u64 q0 = bcast2(qv.x), q1 = bcast2(qv.y),
                q2 = bcast2(qv.z), q3 = bcast2(qv.w);
            ffma2(Sp[0][0], q0, kv.x); ffma2(Sp[0][1], q0, kv.y);
            ffma2(Sp[1][0], q1, kv.x); ffma2(Sp[1][1], q1, kv.y);
            ffma2(Sp[2][0], q2, kv.x); ffma2(Sp[2][1], q2, kv.y);
            ffma2(Sp[3][0], q3, kv.x); ffma2(Sp[3][1], q3, kv.y);
        }
        float S[4][4];
#pragma unroll
        for (int i = 0; i < 4; i++) {
            unpack2(Sp[i][0], S[i][0], S[i][1]);
            unpack2(Sp[i][1], S[i][2], S[i][3]);
        }

        // scale + mask + local row max
        const int qg0 = qt * 64 + r0;
        const int kg0 = kt * 64 + c0;
        float tmax[4];
#pragma unroll
        for (int i = 0; i < 4; i++) {
            tmax[i] = -1e30f;
#pragma unroll
            for (int j = 0; j < 4; j++) {
                bool masked = (kg0 + j > qg0 + i) || (pm[c0 + j] != 0);
                float v = masked ? -1e30f : S[i][j] * sc;
                S[i][j] = v;
                tmax[i] = fmaxf(tmax[i], v);
            }
        }
#pragma unroll
        for (int off = 8; off >= 1; off >>= 1)
#pragma unroll
            for (int i = 0; i < 4; i++)
                tmax[i] = fmaxf(tmax[i],
                    __shfl_xor_sync(0xffffffffu, tmax[i], off, 16));

        float alpha[4], rsum[4];
#pragma unroll
        for (int i = 0; i < 4; i++) {
            float nm = fmaxf(mrow[i], tmax[i]);
            alpha[i] = __expf(mrow[i] - nm);
            mrow[i] = nm;
            float s_ = 0.f;
#pragma unroll
            for (int j = 0; j < 4; j++) {
                float p = __expf(S[i][j] - nm);
                S[i][j] = p;
                s_ += p;
            }
            rsum[i] = s_;
        }
#pragma unroll
        for (int off = 8; off >= 1; off >>= 1)
#pragma unroll
            for (int i = 0; i < 4; i++)
                rsum[i] += __shfl_xor_sync(0xffffffffu, rsum[i], off, 16);
#pragma unroll
        for (int i = 0; i < 4; i++) {
            lrow[i] = lrow[i] * alpha[i] + rsum[i];
            u64 ap = bcast2(alpha[i]);
            fmul2(O[i][0], ap);
            fmul2(O[i][1], ap);
        }

        __syncthreads();
#pragma unroll
        for (int j = 0; j < 4; j++)
#pragma unroll
            for (int i = 0; i < 4; i++)
                Ks[c0 + j][r0 + i] = S[i][j];
        __syncthreads();

        // O += P V
#pragma unroll 4
        for (int kk = 0; kk < 64; kk++) {
            float4 pv = *(const float4*)&Ks[kk][r0];
            ulonglong2 vv = *(const ulonglong2*)&Vs[kk][c0];
            u64 p0 = bcast2(pv.x), p1 = bcast2(pv.y),
                p2 = bcast2(pv.z), p3 = bcast2(pv.w);
            ffma2(O[0][0], p0, vv.x); ffma2(O[0][1], p0, vv.y);
            ffma2(O[1][0], p1, vv.x); ffma2(O[1][1], p1, vv.y);
            ffma2(O[2][0], p2, vv.x); ffma2(O[2][1], p2, vv.y);
            ffma2(O[3][0], p3, vv.x); ffma2(O[3][1], p3, vv.y);
        }
    }

    // epilogue
#pragma unroll
    for (int i = 0; i < 4; i++) {
        float inv = 1.f / lrow[i];
        int qg = qt * 64 + r0 + i;
        float* op = out + ((size_t)n * LQS + qg) * DM + h * HD + c0;
        float o0, o1, o2, o3;
        unpack2(O[i][0], o0, o1);
        unpack2(O[i][1], o2, o3);
        op[0] = o0 * inv;
        op[1] = o1 * inv;
        op[2] = o2 * inv;
        op[3] = o3 * inv;
    }
}

// ---------------------------------------------------------------------------
extern "C" void kernel_launch(void* const* d_in, const int* in_sizes, int n_in,
                              void* d_out, int out_size) {
    const float* query = (const float*)d_in[0];
    const float* key   = (const float*)d_in[1];
    const float* Wq    = (const float*)d_in[2];
    const float* Wk    = (const float*)d_in[3];
    const float* Wv    = (const float*)d_in[4];
    const int* pad     = (const int*)d_in[6];   // bool -> int32
    float* out = (float*)d_out;

    const int attn_smem = 3 * 64 * 68 * 4;  // 52224 B
    cudaFuncSetAttribute(attn_kernel,
                         cudaFuncAttributeMaxDynamicSharedMemorySize, attn_smem);

    void *pq, *pk, *pv;
    cudaGetSymbolAddress(&pq, g_q);
    cudaGetSymbolAddress(&pk, g_k);
    cudaGetSymbolAddress(&pv, g_v);

    count_kernel<<<NB, 256>>>(pad);

    dim3 pg(DM / 128, (NB * LQS) / 128);  // (8, 32)
    proj_kernel<<<pg, 256>>>(query, Wq, (float*)pq);
    proj_kernel<<<pg, 256>>>(key,   Wk, (float*)pk);
    proj_kernel<<<pg, 256>>>(key,   Wv, (float*)pv);

    dim3 ag(LQS / 64, NH, NB);  // (32, 16, 2)
    attn_kernel<<<ag, 256, attn_smem>>>(pad, out);
}